// round 2
// baseline (speedup 1.0000x reference)
#include <cuda_runtime.h>
#include <cuda_bf16.h>
#include <math.h>

// Problem dims (fixed)
#define T_DIM   32
#define N_BATCH 256
#define D_DIM   512
#define H_DIM   2048
#define M_ROWS  (T_DIM * N_BATCH)   // 8192

#define EPS_BN  1e-5f

// ---------------- scratch (device globals; no allocs allowed) ----------------
__device__ float g_h[(size_t)M_ROWS * H_DIM];   // fc1 pre-activation  (64 MB)
__device__ float g_s[(size_t)M_ROWS * H_DIM];   // layer-1 spikes      (64 MB)
__device__ float g_o[(size_t)M_ROWS * D_DIM];   // fc2 pre-activation  (16 MB)
__device__ float g_psum[8 * H_DIM];
__device__ float g_psq [8 * H_DIM];
__device__ float g_scale[H_DIM];
__device__ float g_shift[H_DIM];

// ---------------- SGEMM: C[m,n] = bias[n] + sum_k A[m,k]*B[n,k] --------------
// A: [M x K] row-major, B: [N x K] row-major (both K-contiguous), C: [M x N].
// 128x128 tile, BK=16, 256 threads, 8x8 per thread, double-buffered smem.
__global__ __launch_bounds__(256)
void sgemm_nt_bias(const float* __restrict__ A, const float* __restrict__ B,
                   const float* __restrict__ bias, float* __restrict__ C,
                   int N, int K)
{
    __shared__ float As[2][16][128];
    __shared__ float Bs[2][16][128];

    const int tid = threadIdx.x;
    const int m0  = blockIdx.y * 128;
    const int n0  = blockIdx.x * 128;
    const int tm  = (tid >> 4) * 8;     // 0..120
    const int tn  = (tid & 15) * 8;     // 0..120

    const int lrow = tid >> 2;          // 0..63
    const int lk4  = (tid & 3) * 4;     // 0,4,8,12

    const float* Aptr = A + (size_t)(m0 + lrow) * K + lk4;
    const float* Bptr = B + (size_t)(n0 + lrow) * K + lk4;
    const size_t rstep = (size_t)64 * K;

    float acc[8][8];
    #pragma unroll
    for (int i = 0; i < 8; i++)
        #pragma unroll
        for (int j = 0; j < 8; j++) acc[i][j] = 0.0f;

    float4 ar0, ar1, br0, br1;

    // prologue: load k-tile 0 into smem buffer 0
    ar0 = *(const float4*)(Aptr);
    ar1 = *(const float4*)(Aptr + rstep);
    br0 = *(const float4*)(Bptr);
    br1 = *(const float4*)(Bptr + rstep);
    #pragma unroll
    for (int j = 0; j < 4; j++) {
        As[0][lk4 + j][lrow]      = ((const float*)&ar0)[j];
        As[0][lk4 + j][lrow + 64] = ((const float*)&ar1)[j];
        Bs[0][lk4 + j][lrow]      = ((const float*)&br0)[j];
        Bs[0][lk4 + j][lrow + 64] = ((const float*)&br1)[j];
    }
    __syncthreads();

    const int nk = K >> 4;
    for (int kt = 0; kt < nk; kt++) {
        const int b = kt & 1;
        if (kt + 1 < nk) {
            const float* Ap = Aptr + (size_t)(kt + 1) * 16;
            const float* Bp = Bptr + (size_t)(kt + 1) * 16;
            ar0 = *(const float4*)(Ap);
            ar1 = *(const float4*)(Ap + rstep);
            br0 = *(const float4*)(Bp);
            br1 = *(const float4*)(Bp + rstep);
        }
        #pragma unroll
        for (int k = 0; k < 16; k++) {
            float4 a0 = *(const float4*)&As[b][k][tm];
            float4 a1 = *(const float4*)&As[b][k][tm + 4];
            float4 b0 = *(const float4*)&Bs[b][k][tn];
            float4 b1 = *(const float4*)&Bs[b][k][tn + 4];
            float av[8] = {a0.x, a0.y, a0.z, a0.w, a1.x, a1.y, a1.z, a1.w};
            float bv[8] = {b0.x, b0.y, b0.z, b0.w, b1.x, b1.y, b1.z, b1.w};
            #pragma unroll
            for (int i = 0; i < 8; i++)
                #pragma unroll
                for (int j = 0; j < 8; j++)
                    acc[i][j] = fmaf(av[i], bv[j], acc[i][j]);
        }
        if (kt + 1 < nk) {
            const int nb = b ^ 1;
            #pragma unroll
            for (int j = 0; j < 4; j++) {
                As[nb][lk4 + j][lrow]      = ((const float*)&ar0)[j];
                As[nb][lk4 + j][lrow + 64] = ((const float*)&ar1)[j];
                Bs[nb][lk4 + j][lrow]      = ((const float*)&br0)[j];
                Bs[nb][lk4 + j][lrow + 64] = ((const float*)&br1)[j];
            }
            __syncthreads();
        }
    }

    // epilogue: add bias, store
    const float4 bb0 = *(const float4*)(bias + n0 + tn);
    const float4 bb1 = *(const float4*)(bias + n0 + tn + 4);
    #pragma unroll
    for (int i = 0; i < 8; i++) {
        float4 c0, c1;
        c0.x = acc[i][0] + bb0.x;  c0.y = acc[i][1] + bb0.y;
        c0.z = acc[i][2] + bb0.z;  c0.w = acc[i][3] + bb0.w;
        c1.x = acc[i][4] + bb1.x;  c1.y = acc[i][5] + bb1.y;
        c1.z = acc[i][6] + bb1.z;  c1.w = acc[i][7] + bb1.w;
        float* cp = C + (size_t)(m0 + tm + i) * N + n0 + tn;
        *(float4*)(cp)     = c0;
        *(float4*)(cp + 4) = c1;
    }
}

// ---------------- BN stats: deterministic hierarchical reduction -------------
// grid: (C/32, 8). Block = 256 threads = 32 channels x 8 row-lanes.
// Chunk = 1024 rows; each thread sums 128 rows in fixed order.
__global__ __launch_bounds__(256)
void bn_stats(const float* __restrict__ X, int C,
              float* __restrict__ psum, float* __restrict__ psq)
{
    __shared__ float ss[8][33];
    __shared__ float sq[8][33];
    const int c_l = threadIdx.x & 31;
    const int r_l = threadIdx.x >> 5;
    const int c   = blockIdx.x * 32 + c_l;
    const int mb  = blockIdx.y * 1024;

    float s = 0.0f, q = 0.0f;
    for (int m = mb + r_l; m < mb + 1024; m += 8) {
        float v = X[(size_t)m * C + c];
        s += v;
        q += v * v;
    }
    ss[r_l][c_l] = s;
    sq[r_l][c_l] = q;
    __syncthreads();
    if (r_l == 0) {
        float ts = 0.0f, tq = 0.0f;
        #pragma unroll
        for (int r = 0; r < 8; r++) { ts += ss[r][c_l]; tq += sq[r][c_l]; }
        psum[blockIdx.y * C + c] = ts;
        psq [blockIdx.y * C + c] = tq;
    }
}

__global__ void bn_final(const float* __restrict__ psum, const float* __restrict__ psq,
                         const float* __restrict__ gamma, const float* __restrict__ beta,
                         float* __restrict__ scale, float* __restrict__ shift, int C)
{
    const int c = blockIdx.x * blockDim.x + threadIdx.x;
    if (c >= C) return;
    float s = 0.0f, q = 0.0f;
    #pragma unroll
    for (int i = 0; i < 8; i++) { s += psum[i * C + c]; q += psq[i * C + c]; }
    const float invM = 1.0f / (float)M_ROWS;
    float mean = s * invM;
    float var  = q * invM - mean * mean;
    float rstd = 1.0f / sqrtf(var + EPS_BN);
    float sc   = gamma[c] * rstd;
    scale[c] = sc;
    shift[c] = beta[c] - mean * sc;
}

// ---------------- fused BN-apply + dual adaptive LIF scan over T -------------
// one thread per (n, c); consecutive threads -> consecutive c (coalesced).
__global__ __launch_bounds__(256)
void bn_lif(const float* __restrict__ X, const float* __restrict__ scale,
            const float* __restrict__ shift, float* __restrict__ S, int C)
{
    const int idx = blockIdx.x * blockDim.x + threadIdx.x;   // over N_BATCH*C
    const int c = idx % C;
    const int n = idx / C;
    const float sc = scale[c];
    const float sh = shift[c];

    float v = 0.0f, a = 0.0f;
    #pragma unroll
    for (int t = 0; t < T_DIM; t++) {
        const size_t off = ((size_t)t * N_BATCH + n) * C + c;
        float u = fmaf(X[off], sc, sh);
        // v = v + (u - v)/2  (exact halving, matches /tau with tau=2)
        v = __fadd_rn(v, __fmul_rn(__fsub_rn(u, v), 0.5f));
        float th = __fadd_rn(1.0f, __fmul_rn(0.1f, a));
        float sp = (v >= th ? 1.0f : 0.0f) - (-v >= th ? 1.0f : 0.0f);
        v = __fsub_rn(v, __fmul_rn(sp, th));
        a = __fadd_rn(__fmul_rn(0.9f, a), fabsf(sp));
        S[off] = sp;
    }
}

// ---------------- launch ----------------
extern "C" void kernel_launch(void* const* d_in, const int* in_sizes, int n_in,
                              void* d_out, int out_size)
{
    const float* x   = (const float*)d_in[0];
    const float* W1  = (const float*)d_in[1];
    const float* b1  = (const float*)d_in[2];
    const float* g1  = (const float*)d_in[3];
    const float* be1 = (const float*)d_in[4];
    const float* W2  = (const float*)d_in[5];
    const float* b2  = (const float*)d_in[6];
    const float* g2  = (const float*)d_in[7];
    const float* be2 = (const float*)d_in[8];
    float* out = (float*)d_out;

    float *h, *s, *o, *psum, *psq, *scale, *shift;
    cudaGetSymbolAddress((void**)&h,     g_h);
    cudaGetSymbolAddress((void**)&s,     g_s);
    cudaGetSymbolAddress((void**)&o,     g_o);
    cudaGetSymbolAddress((void**)&psum,  g_psum);
    cudaGetSymbolAddress((void**)&psq,   g_psq);
    cudaGetSymbolAddress((void**)&scale, g_scale);
    cudaGetSymbolAddress((void**)&shift, g_shift);

    // ---- layer 1: fc1 -> bn1 -> lif1 ----
    sgemm_nt_bias<<<dim3(H_DIM / 128, M_ROWS / 128), 256>>>(x, W1, b1, h, H_DIM, D_DIM);
    bn_stats<<<dim3(H_DIM / 32, 8), 256>>>(h, H_DIM, psum, psq);
    bn_final<<<H_DIM / 256, 256>>>(psum, psq, g1, be1, scale, shift, H_DIM);
    bn_lif<<<(N_BATCH * H_DIM) / 256, 256>>>(h, scale, shift, s, H_DIM);

    // ---- layer 2: fc2 -> bn2 -> lif2 ----
    sgemm_nt_bias<<<dim3(D_DIM / 128, M_ROWS / 128), 256>>>(s, W2, b2, o, D_DIM, H_DIM);
    bn_stats<<<dim3(D_DIM / 32, 8), 256>>>(o, D_DIM, psum, psq);
    bn_final<<<D_DIM / 256, 256>>>(psum, psq, g2, be2, scale, shift, D_DIM);
    bn_lif<<<(N_BATCH * D_DIM) / 256, 256>>>(o, scale, shift, out, D_DIM);
}